// round 10
// baseline (speedup 1.0000x reference)
#include <cuda_runtime.h>

// 7-DOF forward kinematics. R10: two batch elements fused per thread via
// packed f32x2 math (fma.rn.f32x2) - element A in lane-lo, element B in
// lane-hi of every 64-bit register. Halves issue slots per element with
// zero risk of ptxas serializing the ILP (it's inside each instruction).

#define DEG 0.017453292519943295f

typedef unsigned long long u64;

__device__ __forceinline__ u64 pk(float lo, float hi) {
    u64 r; asm("mov.b64 %0, {%1, %2};" : "=l"(r) : "f"(lo), "f"(hi)); return r;
}
__device__ __forceinline__ void upk(float& lo, float& hi, u64 v) {
    asm("mov.b64 {%0, %1}, %2;" : "=f"(lo), "=f"(hi) : "l"(v));
}
__device__ __forceinline__ u64 fma2(u64 a, u64 b, u64 c) {
    u64 d; asm("fma.rn.f32x2 %0, %1, %2, %3;" : "=l"(d) : "l"(a), "l"(b), "l"(c)); return d;
}
__device__ __forceinline__ u64 mul2(u64 a, u64 b) {
    u64 d; asm("mul.rn.f32x2 %0, %1, %2;" : "=l"(d) : "l"(a), "l"(b)); return d;
}
__device__ __forceinline__ u64 add2(u64 a, u64 b) {
    u64 d; asm("add.rn.f32x2 %0, %1, %2;" : "=l"(d) : "l"(a), "l"(b)); return d;
}
__device__ __forceinline__ u64 neg2(u64 a) {
    u64 d; asm("xor.b64 %0, %1, 0x8000000080000000;" : "=l"(d) : "l"(a)); return d;
}

__device__ __forceinline__ void fk_scalar(
    float th0, float th1, float th2, float th3,
    float th4, float th5, float th6,
    float& px, float& py, float& pz, float& vx, float& vy, float& vz)
{
    float r0 = th0 * DEG, r1 = th1 * DEG, r2 = th2 * DEG, r3 = th3 * DEG;
    float r4 = th4 * (-0.5f * DEG);
    float r5 = fmaf(th5, DEG / 4.5f, 10.0f * DEG);
    float r6 = fmaf(th6, DEG / 4.5f, 60.0f * DEG);
    float s0, c0, s1, c1, s2, c2, s3, c3, s4, c4, s5, c5, s6, c6;
    __sincosf(r0, &s0, &c0); __sincosf(r1, &s1, &c1); __sincosf(r2, &s2, &c2);
    __sincosf(r3, &s3, &c3); __sincosf(r4, &s4, &c4); __sincosf(r5, &s5, &c5);
    __sincosf(r6, &s6, &c6);
    float A  = fmaf(6.f, c6, 6.f);
    float Bq = fmaf(6.f, s6, -1.f);
    float p5x = s5 * A + c5 * Bq;
    float p5y = s5 * Bq - c5 * A;
    float s56 = s5 * c6 + c5 * s6;
    float c56 = c5 * c6 - s5 * s6;
    float X = 20.f - p5y, Y = s4 * p5x, vY = s4 * s56;
    float p11x = -c3 * X - s3 * Y;
    float p11y =  s3 * X - c3 * Y;
    float v11x = -c3 * c56 - s3 * vY;
    float v11y =  s3 * c56 - c3 * vY;
    float p12y = c4 * p5x, v12y = c4 * s56;
    float p13x = p11x + 17.5f;
    float p14x = c2 * p13x + s2 * p12y;
    float p14y = c2 * p12y - s2 * p13x;
    float v14x = c2 * v11x + s2 * v12y;
    float v14y = c2 * v12y - s2 * v11x;
    float p16x = p14x + 3.f, p16z = 9.5f - p14y;
    float p17x = c1 * p16x - s1 * p11y;
    float p17y = s1 * p16x + c1 * p11y;
    float v17x = c1 * v14x - s1 * v11y;
    float v17y = s1 * v14x + c1 * v11y;
    float p19y = p17y - 1.5f, p19z = 2.5f - p17x;
    px = -s0 * p16z - c0 * p19y;
    py =  c0 * p16z - s0 * p19y + 5.f;
    pz = p19z + 19.5f;
    vx =  s0 * v14y - c0 * v17y;
    vy = -c0 * v14y - s0 * v17y;
    vz = -v17x;
}

__global__ void __launch_bounds__(256) fk_kernel(
    const float* __restrict__ thetas,   // [B, 7]
    float* __restrict__ out,            // [B*3 points][B*3 vectors]
    int n)
{
    int t = blockIdx.x * 256 + threadIdx.x;   // thread -> elements 2t, 2t+1
    int e = t * 2;
    if (e >= n) return;

    if (e + 2 <= n) {
        // ---- 7x LDG.64: 14 thetas for both elements (8B-aligned) ----
        const float2* g2 = (const float2*)(thetas + e * 7);
        float2 q0 = g2[0], q1 = g2[1], q2 = g2[2], q3 = g2[3];
        float2 q4 = g2[4], q5 = g2[5], q6 = g2[6];
        // element A: q0.x q0.y q1.x q1.y q2.x q2.y q3.x
        // element B: q3.y q4.x q4.y q5.x q5.y q6.x q6.y

        // scalar angle prep + MUFU sincos, then pack (A,B) pairs
        float sA[7], cA[7];   // small fixed arrays fully unrolled -> registers
        {
            float ra0 = q0.x * DEG, rb0 = q3.y * DEG;
            float ra1 = q0.y * DEG, rb1 = q4.x * DEG;
            float ra2 = q1.x * DEG, rb2 = q4.y * DEG;
            float ra3 = q1.y * DEG, rb3 = q5.x * DEG;
            float ra4 = q2.x * (-0.5f * DEG), rb4 = q5.y * (-0.5f * DEG);
            float ra5 = fmaf(q2.y, DEG / 4.5f, 10.0f * DEG), rb5 = fmaf(q6.x, DEG / 4.5f, 10.0f * DEG);
            float ra6 = fmaf(q3.x, DEG / 4.5f, 60.0f * DEG), rb6 = fmaf(q6.y, DEG / 4.5f, 60.0f * DEG);
            float xa, ya, xb, yb;
            __sincosf(ra0, &xa, &ya); __sincosf(rb0, &xb, &yb); sA[0]=xa; cA[0]=ya; sA[0]=xa;
            u64 s0p = pk(xa, xb), c0p = pk(ya, yb);
            __sincosf(ra1, &xa, &ya); __sincosf(rb1, &xb, &yb);
            u64 s1p = pk(xa, xb), c1p = pk(ya, yb);
            __sincosf(ra2, &xa, &ya); __sincosf(rb2, &xb, &yb);
            u64 s2p = pk(xa, xb), c2p = pk(ya, yb);
            __sincosf(ra3, &xa, &ya); __sincosf(rb3, &xb, &yb);
            u64 s3p = pk(xa, xb), c3p = pk(ya, yb);
            __sincosf(ra4, &xa, &ya); __sincosf(rb4, &xb, &yb);
            u64 s4p = pk(xa, xb), c4p = pk(ya, yb);
            __sincosf(ra5, &xa, &ya); __sincosf(rb5, &xb, &yb);
            u64 s5p = pk(xa, xb), c5p = pk(ya, yb);
            __sincosf(ra6, &xa, &ya); __sincosf(rb6, &xb, &yb);
            u64 s6p = pk(xa, xb), c6p = pk(ya, yb);

            // packed constants (both lanes equal)
            const u64 C6   = pk(6.f, 6.f);
            const u64 CM1  = pk(-1.f, -1.f);
            const u64 C20  = pk(20.f, 20.f);
            const u64 C175 = pk(17.5f, 17.5f);
            const u64 C3   = pk(3.f, 3.f);
            const u64 C95  = pk(9.5f, 9.5f);
            const u64 CM15 = pk(-1.5f, -1.5f);
            const u64 C25  = pk(2.5f, 2.5f);
            const u64 C5   = pk(5.f, 5.f);
            const u64 C195 = pk(19.5f, 19.5f);

            // ---- folded chain, packed (both elements at once) ----
            u64 A   = fma2(c6p, C6, C6);                       // 6*c6+6
            u64 Bq  = fma2(s6p, C6, CM1);                      // 6*s6-1
            u64 p5x = fma2(c5p, Bq, mul2(s5p, A));             // s5*A + c5*Bq
            u64 p5y = fma2(s5p, Bq, neg2(mul2(c5p, A)));       // s5*Bq - c5*A
            u64 s56 = fma2(s5p, c6p, mul2(c5p, s6p));
            u64 c56 = fma2(c5p, c6p, neg2(mul2(s5p, s6p)));
            u64 X   = fma2(p5y, CM1, C20);                     // 20 - p5y
            u64 Y   = mul2(s4p, p5x);
            u64 vY  = mul2(s4p, s56);
            u64 p11x = neg2(fma2(c3p, X, mul2(s3p, Y)));       // -c3*X - s3*Y
            u64 p11y = fma2(s3p, X, neg2(mul2(c3p, Y)));       //  s3*X - c3*Y
            u64 v11x = neg2(fma2(c3p, c56, mul2(s3p, vY)));
            u64 v11y = fma2(s3p, c56, neg2(mul2(c3p, vY)));
            u64 p12y = mul2(c4p, p5x);
            u64 v12y = mul2(c4p, s56);
            u64 p13x = add2(p11x, C175);
            u64 p14x = fma2(c2p, p13x, mul2(s2p, p12y));
            u64 p14y = fma2(c2p, p12y, neg2(mul2(s2p, p13x)));
            u64 v14x = fma2(c2p, v11x, mul2(s2p, v12y));
            u64 v14y = fma2(c2p, v12y, neg2(mul2(s2p, v11x)));
            u64 p16x = add2(p14x, C3);
            u64 p16z = fma2(p14y, CM1, C95);                   // 9.5 - p14y
            u64 p17x = fma2(c1p, p16x, neg2(mul2(s1p, p11y)));
            u64 p17y = fma2(s1p, p16x, mul2(c1p, p11y));
            u64 v17x = fma2(c1p, v14x, neg2(mul2(s1p, v11y)));
            u64 v17y = fma2(s1p, v14x, mul2(c1p, v11y));
            u64 p19y = add2(p17y, CM15);
            u64 p19z = fma2(p17x, CM1, C25);                   // 2.5 - p17x
            u64 px = neg2(fma2(s0p, p16z, mul2(c0p, p19y)));   // -(s0*p16z + c0*p19y)
            u64 py = add2(fma2(c0p, p16z, neg2(mul2(s0p, p19y))), C5);
            u64 pz = add2(p19z, C195);
            u64 vx = fma2(s0p, v14y, neg2(mul2(c0p, v17y)));
            u64 vy = neg2(fma2(c0p, v14y, mul2(s0p, v17y)));
            u64 vz = neg2(v17x);

            // ---- unpack and store: 3x STG.64 each for p and v ----
            float pxa, pxb, pya, pyb, pza, pzb;
            upk(pxa, pxb, px); upk(pya, pyb, py); upk(pza, pzb, pz);
            float vxa, vxb, vya, vyb, vza, vzb;
            upk(vxa, vxb, vx); upk(vya, vyb, vy); upk(vza, vzb, vz);

            float2* gp = (float2*)(out + e * 3);               // 24B*t: 8B-aligned
            gp[0] = make_float2(pxa, pya);
            gp[1] = make_float2(pza, pxb);
            gp[2] = make_float2(pyb, pzb);
            float2* gv = (float2*)(out + n * 3 + e * 3);
            gv[0] = make_float2(vxa, vya);
            gv[1] = make_float2(vza, vxb);
            gv[2] = make_float2(vyb, vzb);
        }
    } else {
        // odd tail: single remaining element, scalar path
        int i = e;
        const float* tt = thetas + i * 7;
        float px, py, pz, vx, vy, vz;
        fk_scalar(tt[0], tt[1], tt[2], tt[3], tt[4], tt[5], tt[6],
                  px, py, pz, vx, vy, vz);
        int base = i * 3;
        out[base + 0] = px; out[base + 1] = py; out[base + 2] = pz;
        int vbase = n * 3 + base;
        out[vbase + 0] = vx; out[vbase + 1] = vy; out[vbase + 2] = vz;
    }
}

extern "C" void kernel_launch(void* const* d_in, const int* in_sizes, int n_in,
                              void* d_out, int out_size)
{
    const float* thetas = (const float*)d_in[0];
    float* out = (float*)d_out;
    int n = in_sizes[0] / 7;   // B
    int threads = 256;
    int nthreads = (n + 1) / 2;
    int blocks = (nthreads + threads - 1) / threads;
    fk_kernel<<<blocks, threads>>>(thetas, out, n);
}

// round 11
// speedup vs baseline: 1.1976x; 1.1976x over previous
#include <cuda_runtime.h>

// 7-DOF forward kinematics. R11: R8's winning shape (1 elem/thread, warp-
// private smem input staging, folded math, scalar stores) made PERSISTENT:
// grid = 1184 CTAs (148 SMs x 8 resident), grid-stride over warp-chunks of
// 32 elements, with next chunk's LDG.128s issued before current compute
// (software pipelining hides DRAM latency inside the loop).

#define DEG 0.017453292519943295f
#define NBLK 1184   // 148 SMs * 8 CTAs resident -> exactly one wave

__device__ __forceinline__ void fk_math(
    float th0, float th1, float th2, float th3,
    float th4, float th5, float th6,
    float& px, float& py, float& pz, float& vx, float& vy, float& vz)
{
    float r0 = th0 * DEG, r1 = th1 * DEG, r2 = th2 * DEG, r3 = th3 * DEG;
    float r4 = th4 * (-0.5f * DEG);
    float r5 = fmaf(th5, DEG / 4.5f, 10.0f * DEG);
    float r6 = fmaf(th6, DEG / 4.5f, 60.0f * DEG);
    float s0, c0, s1, c1, s2, c2, s3, c3, s4, c4, s5, c5, s6, c6;
    __sincosf(r0, &s0, &c0); __sincosf(r1, &s1, &c1); __sincosf(r2, &s2, &c2);
    __sincosf(r3, &s3, &c3); __sincosf(r4, &s4, &c4); __sincosf(r5, &s5, &c5);
    __sincosf(r6, &s6, &c6);
    float A  = fmaf(6.f, c6, 6.f);
    float Bq = fmaf(6.f, s6, -1.f);
    float p5x = s5 * A + c5 * Bq;
    float p5y = s5 * Bq - c5 * A;
    float s56 = s5 * c6 + c5 * s6;
    float c56 = c5 * c6 - s5 * s6;
    float X = 20.f - p5y, Y = s4 * p5x, vY = s4 * s56;
    float p11x = -c3 * X - s3 * Y;
    float p11y =  s3 * X - c3 * Y;
    float v11x = -c3 * c56 - s3 * vY;
    float v11y =  s3 * c56 - c3 * vY;
    float p12y = c4 * p5x, v12y = c4 * s56;
    float p13x = p11x + 17.5f;
    float p14x = c2 * p13x + s2 * p12y;
    float p14y = c2 * p12y - s2 * p13x;
    float v14x = c2 * v11x + s2 * v12y;
    float v14y = c2 * v12y - s2 * v11x;
    float p16x = p14x + 3.f, p16z = 9.5f - p14y;
    float p17x = c1 * p16x - s1 * p11y;
    float p17y = s1 * p16x + c1 * p11y;
    float v17x = c1 * v14x - s1 * v11y;
    float v17y = s1 * v14x + c1 * v11y;
    float p19y = p17y - 1.5f, p19z = 2.5f - p17x;
    px = -s0 * p16z - c0 * p19y;
    py =  c0 * p16z - s0 * p19y + 5.f;
    pz = p19z + 19.5f;
    vx =  s0 * v14y - c0 * v17y;
    vy = -c0 * v14y - s0 * v17y;
    vz = -v17x;
}

__global__ void __launch_bounds__(256) fk_kernel(
    const float* __restrict__ thetas,   // [B, 7]
    float* __restrict__ out,            // [B*3 points][B*3 vectors]
    int n)
{
    __shared__ float4 stage[8][56];     // per-warp 224 floats

    int warp = threadIdx.x >> 5;
    int lane = threadIdx.x & 31;
    int w = blockIdx.x * 8 + warp;      // global warp id, [0, NBLK*8)
    const int nwarps = NBLK * 8;        // 9472
    int nchunks = n >> 5;               // full 32-element chunks
    int rem = n & 31;

    // ---- prologue: issue first chunk's loads ----
    int chunk = w;
    float4 f4a, f4b;
    bool have = (chunk < nchunks);
    if (have) {
        const float4* g4 = (const float4*)(thetas + (chunk << 5) * 7);
        f4a = g4[lane];
        if (lane < 24) f4b = g4[32 + lane];
    }

    while (have) {
        int wbase = chunk << 5;
        // stage current chunk
        stage[warp][lane] = f4a;
        if (lane < 24) stage[warp][32 + lane] = f4b;
        __syncwarp();
        const float* t = (const float*)stage[warp] + lane * 7;  // conflict-free
        float th0 = t[0], th1 = t[1], th2 = t[2], th3 = t[3];
        float th4 = t[4], th5 = t[5], th6 = t[6];
        __syncwarp();   // all LDS done before next iter's STS overwrites

        // ---- software pipeline: issue NEXT chunk's loads now ----
        int next = chunk + nwarps;
        bool have_next = (next < nchunks);
        if (have_next) {
            const float4* g4 = (const float4*)(thetas + (next << 5) * 7);
            f4a = g4[lane];
            if (lane < 24) f4b = g4[32 + lane];
        }

        // compute current chunk (overlaps the in-flight loads)
        float px, py, pz, vx, vy, vz;
        fk_math(th0, th1, th2, th3, th4, th5, th6, px, py, pz, vx, vy, vz);

        int i = wbase + lane;
        int base = i * 3;
        out[base + 0] = px;
        out[base + 1] = py;
        out[base + 2] = pz;
        int vbase = n * 3 + base;
        out[vbase + 0] = vx;
        out[vbase + 1] = vy;
        out[vbase + 2] = vz;

        chunk = next;
        have = have_next;
    }

    // ---- remainder elements (n not divisible by 32): warp 0 of block 0 ----
    if (rem && w == 0 && lane < rem) {
        int i = (nchunks << 5) + lane;
        const float* tt = thetas + i * 7;
        float px, py, pz, vx, vy, vz;
        fk_math(tt[0], tt[1], tt[2], tt[3], tt[4], tt[5], tt[6],
                px, py, pz, vx, vy, vz);
        int base = i * 3;
        out[base + 0] = px; out[base + 1] = py; out[base + 2] = pz;
        int vbase = n * 3 + base;
        out[vbase + 0] = vx; out[vbase + 1] = vy; out[vbase + 2] = vz;
    }
}

extern "C" void kernel_launch(void* const* d_in, const int* in_sizes, int n_in,
                              void* d_out, int out_size)
{
    const float* thetas = (const float*)d_in[0];
    float* out = (float*)d_out;
    int n = in_sizes[0] / 7;   // B
    fk_kernel<<<NBLK, 256>>>(thetas, out, n);
}